// round 4
// baseline (speedup 1.0000x reference)
#include <cuda_runtime.h>
#include <cstdint>

// Problem constants (fixed by reference)
#define NB 4096
#define NN 128
#define NH 32
#define WARPS_PER_CTA 16
#define CTA_THREADS (WARPS_PER_CTA * 32)

// Bit-packed adjacency: for each (b, node), 128 bits over d = parents mask.
__device__ unsigned int g_packed[(size_t)NB * NN * 4];

// ---------------------------------------------------------------------------
// Kernel 1: bit-pack A (coalesced read of 256MB, write 8MB). HBM-bound.
// ---------------------------------------------------------------------------
__global__ void pack_kernel(const float* __restrict__ A) {
    int node = threadIdx.x;
    int bw   = blockIdx.x;
    int b    = bw >> 2;
    int w    = bw & 3;
    const float* Ab = A + (size_t)b * NN * NN;
    unsigned int word = 0;
#pragma unroll
    for (int j = 0; j < 32; j++) {
        float v = __ldg(&Ab[(size_t)(w * 32 + j) * NN + node]);
        word |= (v != 0.0f ? 1u : 0u) << j;
    }
    g_packed[((size_t)(b * NN + node) << 2) + w] = word;
}

// ---------------------------------------------------------------------------
// Kernel 2: one warp per batch element; lane = hidden channel.
// Node tables (b1, W2, xw, b2) staged in shared memory once per CTA.
// Register-resident outputs; value+offset compaction; shfl butterfly reduce.
// ---------------------------------------------------------------------------
// Dynamic smem layout (floats):
//   s_b1 [128*32]  s_w2 [128*32]  s_xw [128*32]  s_b2 [128]
//   s_ord[16*128] (int)  s_list[16][2][132] (float2)
#define SMEM_BYTES ((4096 * 3 + 128 + WARPS_PER_CTA * 128) * 4 \
                    + WARPS_PER_CTA * 2 * 132 * 8)

__global__ __launch_bounds__(CTA_THREADS, 2)
void chain_kernel(const float* __restrict__ x,
                  const float* __restrict__ u,
                  const float* __restrict__ W1,   // (128,129,32)
                  const float* __restrict__ b1,   // (128,32)
                  const float* __restrict__ W2,   // (128,32,1)
                  const float* __restrict__ b2,   // (128,1)
                  const int*   __restrict__ order,
                  const int*   __restrict__ do_idxs,
                  float* __restrict__ out,
                  int B)
{
    extern __shared__ char smem_raw[];
    float*  s_b1  = reinterpret_cast<float*>(smem_raw);
    float*  s_w2  = s_b1 + 4096;
    float*  s_xw  = s_w2 + 4096;
    float*  s_b2  = s_xw + 4096;
    int*    s_ordb= reinterpret_cast<int*>(s_b2 + 128);
    float2* s_lst = reinterpret_cast<float2*>(s_ordb + WARPS_PER_CTA * 128);

    const int tid  = threadIdx.x;
    const int warp = tid >> 5;
    const int lane = tid & 31;
    const int b    = blockIdx.x * WARPS_PER_CTA + warp;

    // ---- stage node tables into shared (whole CTA cooperates) ----
#pragma unroll
    for (int i = tid; i < 4096; i += CTA_THREADS) {
        int node = i >> 5, h = i & 31;
        s_b1[i] = __ldg(&b1[i]);
        s_w2[i] = __ldg(&W2[i]);
        s_xw[i] = __ldg(&W1[(size_t)node * 129 * NH + 128 * NH + h]);
    }
    if (tid < 128) s_b2[tid] = __ldg(&b2[tid]);

    int* sord = s_ordb + warp * 128;
    if (b < B) {
        const int* ob = order + (size_t)b * NN;
#pragma unroll
        for (int k = 0; k < 4; k++) sord[k * 32 + lane] = __ldg(&ob[k * 32 + lane]);
    }
    __syncthreads();
    if (b >= B) return;

    const int   do_idx = do_idxs[b];
    const float ub     = u[b];
    const float* xb    = x + (size_t)b * NN;

    float so0, so1, so2, so3;          // outputs, lane owns {lane, 32+lane, ...}
    float xr0, xr1, xr2, xr3;          // x row cached in registers
    so0 = (lane      == do_idx) ? ub : 0.0f;
    so1 = (32 + lane == do_idx) ? ub : 0.0f;
    so2 = (64 + lane == do_idx) ? ub : 0.0f;
    so3 = (96 + lane == do_idx) ? ub : 0.0f;
    xr0 = __ldg(&xb[lane]);      xr1 = __ldg(&xb[32 + lane]);
    xr2 = __ldg(&xb[64 + lane]); xr3 = __ldg(&xb[96 + lane]);

    const int off0 = lane * 128;       // W1 byte offsets (d * 32 floats * 4B)
    const int off1 = off0 + 4096;
    const int off2 = off0 + 8192;
    const int off3 = off0 + 12288;

    unsigned int nz0 = 0, nz1 = 0, nz2 = 0, nz3 = 0;
    if (do_idx >= 0) {
        unsigned int bit = 1u << (do_idx & 31);
        if      ((do_idx >> 5) == 0) nz0 = bit;
        else if ((do_idx >> 5) == 1) nz1 = bit;
        else if ((do_idx >> 5) == 2) nz2 = bit;
        else                         nz3 = bit;
    }

    const uint4* pk = reinterpret_cast<const uint4*>(g_packed + (size_t)b * NN * 4);
    const unsigned int lanebit = 1u << lane;
    const unsigned int below   = lanebit - 1u;

    // prefetch mask for step 0
    int   node_p = sord[0];
    uint4 mw_p   = __ldg(&pk[node_p]);

    for (int t = 0; t < NN; t++) {
        const int   node = node_p;
        const uint4 mw   = mw_p;
        if (t + 1 < NN) {                       // prefetch next mask (L2)
            node_p = sord[t + 1];
            mw_p   = __ldg(&pk[node_p]);
        }

        if (node != do_idx) {
            unsigned int m0 = mw.x & nz0;
            unsigned int m1 = mw.y & nz1;
            unsigned int m2 = mw.z & nz2;
            unsigned int m3 = mw.w & nz3;
            int c0 = __popc(m0), c1 = __popc(m1), c2 = __popc(m2), c3 = __popc(m3);
            const int cnt = c0 + c1 + c2 + c3;

            float2* buf = s_lst + (warp * 2 + (t & 1)) * 132;
            if (m0 & lanebit) buf[           __popc(m0 & below)] = make_float2(so0, __int_as_float(off0));
            if (m1 & lanebit) buf[c0 +       __popc(m1 & below)] = make_float2(so1, __int_as_float(off1));
            if (m2 & lanebit) buf[c0+c1 +    __popc(m2 & below)] = make_float2(so2, __int_as_float(off2));
            if (m3 & lanebit) buf[c0+c1+c2 + __popc(m3 & below)] = make_float2(so3, __int_as_float(off3));
            if (lane < 3)     buf[cnt + lane] = make_float2(0.0f, __int_as_float(0));
            __syncwarp();

            // per-node scalars from shared tables (conflict-free LDS)
            const int ti  = node * NH + lane;
            const float b1v = s_b1[ti];
            const float w2v = s_w2[ti];
            const float wxv = s_xw[ti];
            const float b2v = s_b2[node];

            // x[node] via register shuffle (node warp-uniform)
            int wsel = node >> 5;
            float xs = (wsel == 0) ? xr0 : (wsel == 1) ? xr1 : (wsel == 2) ? xr2 : xr3;
            float xv = __shfl_sync(0xffffffffu, xs, node & 31);

            float acc = fmaf(xv, wxv, b1v);

            const float4* bf4 = reinterpret_cast<const float4*>(buf);
            const char*   wb  = reinterpret_cast<const char*>(W1 + (size_t)node * 129 * NH + lane);
            const int iters = (cnt + 3) >> 2;
            for (int it = 0; it < iters; it++) {
                float4 pa = bf4[it * 2];       // {o0, off0, o1, off1}
                float4 pb = bf4[it * 2 + 1];   // {o2, off2, o3, off3}
                float v0 = __ldg(reinterpret_cast<const float*>(wb + __float_as_int(pa.y)));
                float v1 = __ldg(reinterpret_cast<const float*>(wb + __float_as_int(pa.w)));
                float v2 = __ldg(reinterpret_cast<const float*>(wb + __float_as_int(pb.y)));
                float v3 = __ldg(reinterpret_cast<const float*>(wb + __float_as_int(pb.w)));
                acc = fmaf(pa.x, v0, acc);
                acc = fmaf(pa.z, v1, acc);
                acc = fmaf(pb.x, v2, acc);
                acc = fmaf(pb.z, v3, acc);
            }

            float h = acc > 0.0f ? acc : 0.01f * acc;
            float p = h * w2v;
            p += __shfl_xor_sync(0xffffffffu, p, 16);
            p += __shfl_xor_sync(0xffffffffu, p, 8);
            p += __shfl_xor_sync(0xffffffffu, p, 4);
            p += __shfl_xor_sync(0xffffffffu, p, 2);
            p += __shfl_xor_sync(0xffffffffu, p, 1);
            float outv = p + b2v;              // all lanes hold result

            if ((node & 31) == lane) {
                if      (wsel == 0) so0 = outv;
                else if (wsel == 1) so1 = outv;
                else if (wsel == 2) so2 = outv;
                else                so3 = outv;
            }
        }

        unsigned int bit = 1u << (node & 31);
        int ws = node >> 5;
        if      (ws == 0) nz0 |= bit;
        else if (ws == 1) nz1 |= bit;
        else if (ws == 2) nz2 |= bit;
        else              nz3 |= bit;
    }

    out[(size_t)b * NN +       lane] = so0;
    out[(size_t)b * NN +  32 + lane] = so1;
    out[(size_t)b * NN +  64 + lane] = so2;
    out[(size_t)b * NN +  96 + lane] = so3;
}

// ---------------------------------------------------------------------------
// inputs (metadata order): x, A, u, W1, b1, W2, b2, order, do_idxs
// ---------------------------------------------------------------------------
extern "C" void kernel_launch(void* const* d_in, const int* in_sizes, int n_in,
                              void* d_out, int out_size) {
    const float* x   = (const float*)d_in[0];
    const float* A   = (const float*)d_in[1];
    const float* u   = (const float*)d_in[2];
    const float* W1  = (const float*)d_in[3];
    const float* b1  = (const float*)d_in[4];
    const float* W2  = (const float*)d_in[5];
    const float* b2  = (const float*)d_in[6];
    const int*   ord = (const int*)d_in[7];
    const int*   doi = (const int*)d_in[8];
    float* out = (float*)d_out;

    int B = in_sizes[2];
    if (B > NB) B = NB;

    static bool attr_set = false;
    if (!attr_set) {
        cudaFuncSetAttribute(chain_kernel,
                             cudaFuncAttributeMaxDynamicSharedMemorySize,
                             SMEM_BYTES);
        attr_set = true;
    }

    pack_kernel<<<B * 4, 128>>>(A);

    int grid = (B + WARPS_PER_CTA - 1) / WARPS_PER_CTA;
    chain_kernel<<<grid, CTA_THREADS, SMEM_BYTES>>>(x, u, W1, b1, W2, b2,
                                                    ord, doi, out, B);
}